// round 1
// baseline (speedup 1.0000x reference)
#include <cuda_runtime.h>
#include <math.h>

// Problem dims (fixed for this dataset)
#define B_   64
#define T_   512
#define IN_  512
#define HID_ 1024
#define OUT_ 512

// Scratch (allocation-free contract: __device__ globals)
__device__ float g_xp[(size_t)T_ * B_ * HID_];    // [t][b][j]  input projection
__device__ float g_hseq[(size_t)T_ * B_ * HID_];  // [t][b][j]  hidden states (for final out GEMM)
__device__ float g_hT[2][HID_ * B_];              // ping-pong transposed hidden [j][b]

// ---------------------------------------------------------------------------
// GEMM A: xp[t][b][j] = sum_i input[b][t][i] * W_ih[j][i] + bias[j]
// M = B*T (m = b*T + t, contiguous rows in input), N = HID, K = IN
// block tile 64x64, 256 threads, thread tile 4x4, k-chunk 16
// ---------------------------------------------------------------------------
__global__ void gemm_in_kernel(const float* __restrict__ in,
                               const float* __restrict__ W,
                               const float* __restrict__ bias) {
    __shared__ float sA[16][68];
    __shared__ float sB[16][68];
    const int m0 = blockIdx.y * 64;
    const int n0 = blockIdx.x * 64;
    const int tid = threadIdx.x;
    const int tx = tid & 15;
    const int ty = tid >> 4;
    const int r  = tid >> 2;   // 0..63
    const int kq = tid & 3;    // 0..3

    float acc[4][4] = {};

    for (int k0 = 0; k0 < IN_; k0 += 16) {
        float4 va = *reinterpret_cast<const float4*>(&in[(size_t)(m0 + r) * IN_ + k0 + kq * 4]);
        float4 vb = *reinterpret_cast<const float4*>(&W [(size_t)(n0 + r) * IN_ + k0 + kq * 4]);
        sA[kq * 4 + 0][r] = va.x; sA[kq * 4 + 1][r] = va.y;
        sA[kq * 4 + 2][r] = va.z; sA[kq * 4 + 3][r] = va.w;
        sB[kq * 4 + 0][r] = vb.x; sB[kq * 4 + 1][r] = vb.y;
        sB[kq * 4 + 2][r] = vb.z; sB[kq * 4 + 3][r] = vb.w;
        __syncthreads();
        #pragma unroll
        for (int kk = 0; kk < 16; kk++) {
            float4 a  = *reinterpret_cast<const float4*>(&sA[kk][ty * 4]);
            float4 b4 = *reinterpret_cast<const float4*>(&sB[kk][tx * 4]);
            acc[0][0] += a.x * b4.x; acc[0][1] += a.x * b4.y; acc[0][2] += a.x * b4.z; acc[0][3] += a.x * b4.w;
            acc[1][0] += a.y * b4.x; acc[1][1] += a.y * b4.y; acc[1][2] += a.y * b4.z; acc[1][3] += a.y * b4.w;
            acc[2][0] += a.z * b4.x; acc[2][1] += a.z * b4.y; acc[2][2] += a.z * b4.z; acc[2][3] += a.z * b4.w;
            acc[3][0] += a.w * b4.x; acc[3][1] += a.w * b4.y; acc[3][2] += a.w * b4.z; acc[3][3] += a.w * b4.w;
        }
        __syncthreads();
    }

    #pragma unroll
    for (int i = 0; i < 4; i++) {
        const int m = m0 + ty * 4 + i;
        const int bb = m >> 9;        // m / T_
        const int tt = m & (T_ - 1);  // m % T_
        float* dst = &g_xp[((size_t)tt * B_ + bb) * HID_ + n0 + tx * 4];
        #pragma unroll
        for (int jj = 0; jj < 4; jj++)
            dst[jj] = acc[i][jj] + bias[n0 + tx * 4 + jj];
    }
}

// ---------------------------------------------------------------------------
// step 0: h_0 = tanh(xp_0)  (h_prev = 0)
// ---------------------------------------------------------------------------
__global__ void step0_kernel() {
    const int i = blockIdx.x * blockDim.x + threadIdx.x;  // over B*HID (t=0 slice is flat prefix)
    const float v = tanhf(g_xp[i]);
    g_hseq[i] = v;
    const int b = i >> 10;           // i / HID_
    const int j = i & (HID_ - 1);    // i % HID_
    g_hT[0][j * B_ + b] = v;
}

// ---------------------------------------------------------------------------
// Recurrent step t (t >= 1):
//   h_t[b][j] = tanh(xp_t[b][j] + sum_k h_{t-1}[b][k] * W_hh[j][k])
// reads transposed hT_prev[k][b]; writes hseq[t] (row-major) and hT_cur.
// grid = HID/8 = 128 blocks x 128 threads; block tile 64b x 8j;
// thread tile = 4 consecutive b (one LDS.128) x 1 j.
// ---------------------------------------------------------------------------
__global__ void step_kernel(int t, const float* __restrict__ Whh) {
    const float* __restrict__ hTp = g_hT[(t - 1) & 1];
    float* __restrict__ hTc = g_hT[t & 1];
    const float* __restrict__ xp = g_xp + (size_t)t * B_ * HID_;
    float* __restrict__ hs = g_hseq + (size_t)t * B_ * HID_;

    __shared__ float sh[32][64];   // [kk][b]
    __shared__ float sw[8][36];    // [j][kk]  (pad 36: conflict-free, float4-aligned)

    const int tid = threadIdx.x;   // 128
    const int tc = tid & 7;        // output col within tile
    const int tb = tid >> 3;       // 0..15, owns b = 4*tb .. 4*tb+3
    const int j0 = blockIdx.x * 8;

    float a0 = 0.f, a1 = 0.f, a2 = 0.f, a3 = 0.f;

    for (int k0 = 0; k0 < HID_; k0 += 32) {
        // stage h chunk [32 k][64 b]  (coalesced: hT is k-major)
        #pragma unroll
        for (int q = 0; q < 4; q++) {
            const int idx = tid + q * 128;   // 0..511 float4s
            const int rr = idx >> 4;         // 0..31
            const int c4 = idx & 15;
            *reinterpret_cast<float4*>(&sh[rr][c4 * 4]) =
                *reinterpret_cast<const float4*>(&hTp[(k0 + rr) * B_ + c4 * 4]);
        }
        // stage W chunk [8 j][32 k]
        if (tid < 64) {
            const int rr = tid >> 3;   // 0..7
            const int kq = tid & 7;    // 0..7
            *reinterpret_cast<float4*>(&sw[rr][kq * 4]) =
                *reinterpret_cast<const float4*>(&Whh[(size_t)(j0 + rr) * HID_ + k0 + kq * 4]);
        }
        __syncthreads();
        #pragma unroll
        for (int kk = 0; kk < 32; kk++) {
            const float4 hv = *reinterpret_cast<const float4*>(&sh[kk][tb * 4]);
            const float wv = sw[tc][kk];
            a0 += hv.x * wv; a1 += hv.y * wv; a2 += hv.z * wv; a3 += hv.w * wv;
        }
        __syncthreads();
    }

    const int j = j0 + tc;
    const int b0 = tb * 4;
    const float r0 = tanhf(a0 + xp[(b0 + 0) * HID_ + j]);
    const float r1 = tanhf(a1 + xp[(b0 + 1) * HID_ + j]);
    const float r2 = tanhf(a2 + xp[(b0 + 2) * HID_ + j]);
    const float r3 = tanhf(a3 + xp[(b0 + 3) * HID_ + j]);
    hs[(b0 + 0) * HID_ + j] = r0;
    hs[(b0 + 1) * HID_ + j] = r1;
    hs[(b0 + 2) * HID_ + j] = r2;
    hs[(b0 + 3) * HID_ + j] = r3;
    *reinterpret_cast<float4*>(&hTc[j * B_ + b0]) = make_float4(r0, r1, r2, r3);
}

// ---------------------------------------------------------------------------
// GEMM C: out[b][t][o] = sum_j hseq[t][b][j] * W_out[o][j] + b_out[o]
// M = T*B (m = t*B + b, contiguous rows in g_hseq), N = OUT, K = HID
// ---------------------------------------------------------------------------
__global__ void gemm_out_kernel(const float* __restrict__ Wout,
                                const float* __restrict__ bout,
                                float* __restrict__ out) {
    __shared__ float sA[16][68];
    __shared__ float sB[16][68];
    const int m0 = blockIdx.y * 64;
    const int n0 = blockIdx.x * 64;
    const int tid = threadIdx.x;
    const int tx = tid & 15;
    const int ty = tid >> 4;
    const int r  = tid >> 2;
    const int kq = tid & 3;

    float acc[4][4] = {};

    for (int k0 = 0; k0 < HID_; k0 += 16) {
        float4 va = *reinterpret_cast<const float4*>(&g_hseq[(size_t)(m0 + r) * HID_ + k0 + kq * 4]);
        float4 vb = *reinterpret_cast<const float4*>(&Wout  [(size_t)(n0 + r) * HID_ + k0 + kq * 4]);
        sA[kq * 4 + 0][r] = va.x; sA[kq * 4 + 1][r] = va.y;
        sA[kq * 4 + 2][r] = va.z; sA[kq * 4 + 3][r] = va.w;
        sB[kq * 4 + 0][r] = vb.x; sB[kq * 4 + 1][r] = vb.y;
        sB[kq * 4 + 2][r] = vb.z; sB[kq * 4 + 3][r] = vb.w;
        __syncthreads();
        #pragma unroll
        for (int kk = 0; kk < 16; kk++) {
            float4 a  = *reinterpret_cast<const float4*>(&sA[kk][ty * 4]);
            float4 b4 = *reinterpret_cast<const float4*>(&sB[kk][tx * 4]);
            acc[0][0] += a.x * b4.x; acc[0][1] += a.x * b4.y; acc[0][2] += a.x * b4.z; acc[0][3] += a.x * b4.w;
            acc[1][0] += a.y * b4.x; acc[1][1] += a.y * b4.y; acc[1][2] += a.y * b4.z; acc[1][3] += a.y * b4.w;
            acc[2][0] += a.z * b4.x; acc[2][1] += a.z * b4.y; acc[2][2] += a.z * b4.z; acc[2][3] += a.z * b4.w;
            acc[3][0] += a.w * b4.x; acc[3][1] += a.w * b4.y; acc[3][2] += a.w * b4.z; acc[3][3] += a.w * b4.w;
        }
        __syncthreads();
    }

    #pragma unroll
    for (int i = 0; i < 4; i++) {
        const int m = m0 + ty * 4 + i;
        const int tt = m >> 6;        // m / B_
        const int bb = m & (B_ - 1);  // m % B_
        float* dst = &out[((size_t)bb * T_ + tt) * OUT_ + n0 + tx * 4];
        #pragma unroll
        for (int jj = 0; jj < 4; jj++)
            dst[jj] = acc[i][jj] + bout[n0 + tx * 4 + jj];
    }
}

// ---------------------------------------------------------------------------
extern "C" void kernel_launch(void* const* d_in, const int* in_sizes, int n_in,
                              void* d_out, int out_size) {
    const float* input = (const float*)d_in[0];
    const float* W_ih  = (const float*)d_in[1];
    const float* W_hh  = (const float*)d_in[2];
    const float* bias  = (const float*)d_in[3];
    const float* W_out = (const float*)d_in[4];
    const float* b_out = (const float*)d_in[5];
    float* out = (float*)d_out;

    // 1) input projection for all timesteps (one big GEMM)
    gemm_in_kernel<<<dim3(HID_ / 64, (B_ * T_) / 64), 256>>>(input, W_ih, bias);

    // 2) sequential recurrence (out-projection hoisted out of the loop)
    step0_kernel<<<(B_ * HID_) / 256, 256>>>();
    for (int t = 1; t < T_; t++)
        step_kernel<<<HID_ / 8, 128>>>(t, W_hh);

    // 3) output projection for all timesteps (one big GEMM)
    gemm_out_kernel<<<dim3(OUT_ / 64, (B_ * T_) / 64), 256>>>(W_out, b_out, out);
}

// round 3
// speedup vs baseline: 1.8304x; 1.8304x over previous
#include <cuda_runtime.h>
#include <math.h>

// Problem dims (fixed for this dataset)
#define B_   64
#define T_   512
#define IN_  512
#define HID_ 1024
#define OUT_ 512
#define KS_  8          // split-K factor for the recurrent GEMM
#define KSL_ (HID_/KS_) // 128 k per slice
#define NJT_ 16         // j-tiles (HID/64)

// Scratch (allocation-free contract: __device__ globals; BSS zero-init)
__device__ float g_xp[(size_t)T_ * B_ * HID_];    // [t][b][j]  input projection
__device__ float g_hseq[(size_t)T_ * B_ * HID_];  // [t][b][j]  hidden states (for final out GEMM)
__device__ float g_hT[2][HID_ * B_];              // ping-pong transposed hidden [j][b]
__device__ float g_part[KS_][B_ * HID_];          // split-K partial sums
__device__ int   g_cnt[T_ * NJT_];                // arrival counters (reset after each use)

// ---------------------------------------------------------------------------
// GEMM A: xp[t][b][j] = sum_i input[b][t][i] * W_ih[j][i] + bias[j]
// M = B*T (m = b*T + t, contiguous rows in input), N = HID, K = IN
// ---------------------------------------------------------------------------
__global__ void gemm_in_kernel(const float* __restrict__ in,
                               const float* __restrict__ W,
                               const float* __restrict__ bias) {
    __shared__ float sA[16][68];
    __shared__ float sB[16][68];
    const int m0 = blockIdx.y * 64;
    const int n0 = blockIdx.x * 64;
    const int tid = threadIdx.x;
    const int tx = tid & 15;
    const int ty = tid >> 4;
    const int r  = tid >> 2;   // 0..63
    const int kq = tid & 3;    // 0..3

    float acc[4][4] = {};

    for (int k0 = 0; k0 < IN_; k0 += 16) {
        float4 va = *reinterpret_cast<const float4*>(&in[(size_t)(m0 + r) * IN_ + k0 + kq * 4]);
        float4 vb = *reinterpret_cast<const float4*>(&W [(size_t)(n0 + r) * IN_ + k0 + kq * 4]);
        sA[kq * 4 + 0][r] = va.x; sA[kq * 4 + 1][r] = va.y;
        sA[kq * 4 + 2][r] = va.z; sA[kq * 4 + 3][r] = va.w;
        sB[kq * 4 + 0][r] = vb.x; sB[kq * 4 + 1][r] = vb.y;
        sB[kq * 4 + 2][r] = vb.z; sB[kq * 4 + 3][r] = vb.w;
        __syncthreads();
        #pragma unroll
        for (int kk = 0; kk < 16; kk++) {
            float4 a  = *reinterpret_cast<const float4*>(&sA[kk][ty * 4]);
            float4 b4 = *reinterpret_cast<const float4*>(&sB[kk][tx * 4]);
            acc[0][0] += a.x * b4.x; acc[0][1] += a.x * b4.y; acc[0][2] += a.x * b4.z; acc[0][3] += a.x * b4.w;
            acc[1][0] += a.y * b4.x; acc[1][1] += a.y * b4.y; acc[1][2] += a.y * b4.z; acc[1][3] += a.y * b4.w;
            acc[2][0] += a.z * b4.x; acc[2][1] += a.z * b4.y; acc[2][2] += a.z * b4.z; acc[2][3] += a.z * b4.w;
            acc[3][0] += a.w * b4.x; acc[3][1] += a.w * b4.y; acc[3][2] += a.w * b4.z; acc[3][3] += a.w * b4.w;
        }
        __syncthreads();
    }

    #pragma unroll
    for (int i = 0; i < 4; i++) {
        const int m = m0 + ty * 4 + i;
        const int bb = m >> 9;        // m / T_
        const int tt = m & (T_ - 1);  // m % T_
        float* dst = &g_xp[((size_t)tt * B_ + bb) * HID_ + n0 + tx * 4];
        #pragma unroll
        for (int jj = 0; jj < 4; jj++)
            dst[jj] = acc[i][jj] + bias[n0 + tx * 4 + jj];
    }
}

// ---------------------------------------------------------------------------
// step 0: h_0 = tanh(xp_0)  (h_prev = 0)
// ---------------------------------------------------------------------------
__global__ void step0_kernel() {
    const int i = blockIdx.x * blockDim.x + threadIdx.x;  // over B*HID
    const float v = tanhf(g_xp[i]);
    g_hseq[i] = v;
    const int b = i >> 10;           // i / HID_
    const int j = i & (HID_ - 1);    // i % HID_
    g_hT[0][j * B_ + b] = v;
}

// ---------------------------------------------------------------------------
// Fused recurrent step (t >= 1), ONE kernel per step:
//   phase 1 (all 128 blocks): split-K partials
//       part[ks][b][j] = sum_{k in slice ks} hT_{t-1}[k][b] * W_hh[j][k]
//   phase 2 (last-arriving block per j-tile): reduce 8 partials + xp,
//       tanh, write hseq[t] and transposed hT.
// grid = (16 j-tiles, 8 k-slices), 256 threads, block tile 64b x 64j,
// thread tile 4b x 4j, double-buffered smem.
// ---------------------------------------------------------------------------
__global__ __launch_bounds__(256) void step_fused(int t, const float* __restrict__ Whh) {
    const float* __restrict__ hTp = g_hT[(t - 1) & 1];

    __shared__ float sh[2][16][68];  // [buf][k][b]
    __shared__ float sw[2][16][68];  // [buf][k][j]
    __shared__ int s_last;

    const int tid = threadIdx.x;
    const int tx = tid & 15;         // j quad
    const int ty = tid >> 4;         // b quad
    const int jx = blockIdx.x;       // j-tile index
    const int j0 = jx * 64;
    const int k0 = blockIdx.y * KSL_;

    const int hr = tid >> 4;         // 0..15  k-row for h stage
    const int hc = tid & 15;         // 0..15  b float4 for h stage
    const int wr = tid >> 2;         // 0..63  j-row for w stage
    const int wq = tid & 3;          // 0..3   k float4 for w stage

    float acc[4][4] = {};

    // stage chunk 0 into buffer 0
    {
        float4 vh = *reinterpret_cast<const float4*>(&hTp[(k0 + hr) * B_ + hc * 4]);
        *reinterpret_cast<float4*>(&sh[0][hr][hc * 4]) = vh;
        float4 vw = *reinterpret_cast<const float4*>(&Whh[(size_t)(j0 + wr) * HID_ + k0 + wq * 4]);
        sw[0][wq * 4 + 0][wr] = vw.x; sw[0][wq * 4 + 1][wr] = vw.y;
        sw[0][wq * 4 + 2][wr] = vw.z; sw[0][wq * 4 + 3][wr] = vw.w;
    }

    #pragma unroll
    for (int c = 0; c < KSL_ / 16; c++) {
        __syncthreads();
        if (c + 1 < KSL_ / 16) {   // prefetch next chunk into the other buffer
            const int kc = k0 + (c + 1) * 16;
            const int nb = (c + 1) & 1;
            float4 vh = *reinterpret_cast<const float4*>(&hTp[(kc + hr) * B_ + hc * 4]);
            *reinterpret_cast<float4*>(&sh[nb][hr][hc * 4]) = vh;
            float4 vw = *reinterpret_cast<const float4*>(&Whh[(size_t)(j0 + wr) * HID_ + kc + wq * 4]);
            sw[nb][wq * 4 + 0][wr] = vw.x; sw[nb][wq * 4 + 1][wr] = vw.y;
            sw[nb][wq * 4 + 2][wr] = vw.z; sw[nb][wq * 4 + 3][wr] = vw.w;
        }
        const int cb = c & 1;
        #pragma unroll
        for (int kk = 0; kk < 16; kk++) {
            float4 hv = *reinterpret_cast<const float4*>(&sh[cb][kk][ty * 4]);
            float4 wv = *reinterpret_cast<const float4*>(&sw[cb][kk][tx * 4]);
            acc[0][0] += hv.x * wv.x; acc[0][1] += hv.x * wv.y; acc[0][2] += hv.x * wv.z; acc[0][3] += hv.x * wv.w;
            acc[1][0] += hv.y * wv.x; acc[1][1] += hv.y * wv.y; acc[1][2] += hv.y * wv.z; acc[1][3] += hv.y * wv.w;
            acc[2][0] += hv.z * wv.x; acc[2][1] += hv.z * wv.y; acc[2][2] += hv.z * wv.z; acc[2][3] += hv.z * wv.w;
            acc[3][0] += hv.w * wv.x; acc[3][1] += hv.w * wv.y; acc[3][2] += hv.w * wv.z; acc[3][3] += hv.w * wv.w;
        }
    }

    // write partials (each k-slice writes its own buffer -> deterministic)
    float* __restrict__ pdst = g_part[blockIdx.y];
    #pragma unroll
    for (int i = 0; i < 4; i++) {
        const int b = ty * 4 + i;
        *reinterpret_cast<float4*>(&pdst[b * HID_ + j0 + tx * 4]) =
            make_float4(acc[i][0], acc[i][1], acc[i][2], acc[i][3]);
    }

    // ---- last-block reduction handoff (threadFenceReduction pattern) ----
    __threadfence();
    __syncthreads();
    const int cidx = t * NJT_ + jx;
    if (tid == 0)
        s_last = (atomicAdd(&g_cnt[cidx], 1) == KS_ - 1);
    __syncthreads();
    if (!s_last) return;

    __threadfence();   // acquire: make other slices' partials visible

    const float* __restrict__ xp = g_xp + (size_t)t * B_ * HID_;
    float* __restrict__ hs = g_hseq + (size_t)t * B_ * HID_;
    float* __restrict__ hTc = g_hT[t & 1];

    // 64 b x 64 j = 1024 float4s; 4 per thread. j4 fastest -> coalesced rows.
    #pragma unroll
    for (int it = 0; it < 4; it++) {
        const int idx = it * 256 + tid;
        const int b = idx >> 4;
        const int j = j0 + (idx & 15) * 4;
        const size_t off = (size_t)b * HID_ + j;
        float4 s = *reinterpret_cast<const float4*>(&xp[off]);
        #pragma unroll
        for (int ks = 0; ks < KS_; ks++) {
            const float4* p = reinterpret_cast<const float4*>(&g_part[ks][off]);
            float4 v = __ldcg(p);   // bypass L1: cross-block produced data
            s.x += v.x; s.y += v.y; s.z += v.z; s.w += v.w;
        }
        float4 r = make_float4(tanhf(s.x), tanhf(s.y), tanhf(s.z), tanhf(s.w));
        *reinterpret_cast<float4*>(&hs[off]) = r;
        hTc[(j + 0) * B_ + b] = r.x;
        hTc[(j + 1) * B_ + b] = r.y;
        hTc[(j + 2) * B_ + b] = r.z;
        hTc[(j + 3) * B_ + b] = r.w;
    }

    // reset counter for the next graph replay (nobody reads it again this run)
    if (tid == 0) g_cnt[cidx] = 0;
}

// ---------------------------------------------------------------------------
// GEMM C: out[b][t][o] = sum_j hseq[t][b][j] * W_out[o][j] + b_out[o]
// M = T*B (m = t*B + b, contiguous rows in g_hseq), N = OUT, K = HID
// ---------------------------------------------------------------------------
__global__ void gemm_out_kernel(const float* __restrict__ Wout,
                                const float* __restrict__ bout,
                                float* __restrict__ out) {
    __shared__ float sA[16][68];
    __shared__ float sB[16][68];
    const int m0 = blockIdx.y * 64;
    const int n0 = blockIdx.x * 64;
    const int tid = threadIdx.x;
    const int tx = tid & 15;
    const int ty = tid >> 4;
    const int r  = tid >> 2;
    const int kq = tid & 3;

    float acc[4][4] = {};

    for (int k0 = 0; k0 < HID_; k0 += 16) {
        float4 va = *reinterpret_cast<const float4*>(&g_hseq[(size_t)(m0 + r) * HID_ + k0 + kq * 4]);
        float4 vb = *reinterpret_cast<const float4*>(&Wout  [(size_t)(n0 + r) * HID_ + k0 + kq * 4]);
        sA[kq * 4 + 0][r] = va.x; sA[kq * 4 + 1][r] = va.y;
        sA[kq * 4 + 2][r] = va.z; sA[kq * 4 + 3][r] = va.w;
        sB[kq * 4 + 0][r] = vb.x; sB[kq * 4 + 1][r] = vb.y;
        sB[kq * 4 + 2][r] = vb.z; sB[kq * 4 + 3][r] = vb.w;
        __syncthreads();
        #pragma unroll
        for (int kk = 0; kk < 16; kk++) {
            float4 a  = *reinterpret_cast<const float4*>(&sA[kk][ty * 4]);
            float4 b4 = *reinterpret_cast<const float4*>(&sB[kk][tx * 4]);
            acc[0][0] += a.x * b4.x; acc[0][1] += a.x * b4.y; acc[0][2] += a.x * b4.z; acc[0][3] += a.x * b4.w;
            acc[1][0] += a.y * b4.x; acc[1][1] += a.y * b4.y; acc[1][2] += a.y * b4.z; acc[1][3] += a.y * b4.w;
            acc[2][0] += a.z * b4.x; acc[2][1] += a.z * b4.y; acc[2][2] += a.z * b4.z; acc[2][3] += a.z * b4.w;
            acc[3][0] += a.w * b4.x; acc[3][1] += a.w * b4.y; acc[3][2] += a.w * b4.z; acc[3][3] += a.w * b4.w;
        }
        __syncthreads();
    }

    #pragma unroll
    for (int i = 0; i < 4; i++) {
        const int m = m0 + ty * 4 + i;
        const int tt = m >> 6;        // m / B_
        const int bb = m & (B_ - 1);  // m % B_
        float* dst = &out[((size_t)bb * T_ + tt) * OUT_ + n0 + tx * 4];
        #pragma unroll
        for (int jj = 0; jj < 4; jj++)
            dst[jj] = acc[i][jj] + bout[n0 + tx * 4 + jj];
    }
}

// ---------------------------------------------------------------------------
extern "C" void kernel_launch(void* const* d_in, const int* in_sizes, int n_in,
                              void* d_out, int out_size) {
    const float* input = (const float*)d_in[0];
    const float* W_ih  = (const float*)d_in[1];
    const float* W_hh  = (const float*)d_in[2];
    const float* bias  = (const float*)d_in[3];
    const float* W_out = (const float*)d_in[4];
    const float* b_out = (const float*)d_in[5];
    float* out = (float*)d_out;

    // 1) input projection for all timesteps (one big GEMM)
    gemm_in_kernel<<<dim3(HID_ / 64, (B_ * T_) / 64), 256>>>(input, W_ih, bias);

    // 2) sequential recurrence: ONE fused kernel per step (513 graph nodes total)
    step0_kernel<<<(B_ * HID_) / 256, 256>>>();
    for (int t = 1; t < T_; t++)
        step_fused<<<dim3(NJT_, KS_), 256>>>(t, W_hh);

    // 3) output projection for all timesteps (one big GEMM)
    gemm_out_kernel<<<dim3(OUT_ / 64, (B_ * T_) / 64), 256>>>(W_out, b_out, out);
}

// round 4
// speedup vs baseline: 2.2434x; 1.2257x over previous
#include <cuda_runtime.h>
#include <math.h>

// Problem dims (fixed for this dataset)
#define B_   64
#define T_   512
#define IN_  512
#define HID_ 1024
#define OUT_ 512
#define NBLK 128        // persistent blocks (<= 148 SMs -> all co-resident)
#define KS_  16         // split-K slices (64 k each)
#define KSL_ 64
#define JT_  8          // j-tiles of 128

typedef unsigned long long ull;

// packed fp32x2 FMA helpers (bit-identical to scalar FFMA)
#define FMA2(d, a, b) asm("fma.rn.f32x2 %0, %1, %2, %0;" : "+l"(d) : "l"(a), "l"(b))
#define DUP2(d, s)    asm("mov.b64 %0, {%1, %1};" : "=l"(d) : "r"(__float_as_uint(s)))
#define UNPK2(lo, hi, s) asm("mov.b64 {%0, %1}, %2;" : "=f"(lo), "=f"(hi) : "l"(s))

// Scratch (allocation-free contract: __device__ globals; BSS zero-init)
__device__ float g_xp[(size_t)T_ * B_ * HID_];    // [t][b][j]
__device__ float g_hseq[(size_t)T_ * B_ * HID_];  // [t][b][j]
__device__ float g_hT[2][HID_ * B_];              // ping-pong transposed hidden [j][b]
__device__ float g_part[KS_][B_ * HID_];          // split-K partials
__device__ unsigned g_gb_cnt;                     // barrier arrivals (returns to 0)
__device__ unsigned g_gb_phase;                   // barrier phase (monotonic across replays)

__device__ __forceinline__ float ldcg_f(const float* p) {
    float v; asm volatile("ld.global.cg.f32 %0, [%1];" : "=f"(v) : "l"(p)); return v;
}
__device__ __forceinline__ float4 ldcg_f4(const float* p) {
    float4 v;
    asm volatile("ld.global.cg.v4.f32 {%0,%1,%2,%3}, [%4];"
                 : "=f"(v.x), "=f"(v.y), "=f"(v.z), "=f"(v.w) : "l"(p));
    return v;
}
__device__ __forceinline__ void stcg_f4(float* p, float4 v) {
    asm volatile("st.global.cg.v4.f32 [%0], {%1,%2,%3,%4};"
                 :: "l"(p), "f"(v.x), "f"(v.y), "f"(v.z), "f"(v.w));
}

// all-resident grid barrier; base = phase snapshot at kernel entry, ord = 1,2,3...
__device__ __forceinline__ void grid_sync(unsigned base, int ord) {
    __threadfence();           // publish this thread's prior writes
    __syncthreads();
    if (threadIdx.x == 0) {
        unsigned old = atomicAdd(&g_gb_cnt, 1);
        if (old == NBLK - 1) {
            atomicExch(&g_gb_cnt, 0);   // reset BEFORE release -> replay-safe
            __threadfence();
            atomicAdd(&g_gb_phase, 1);
        } else {
            unsigned cur;
            do {
                __nanosleep(64);
                asm volatile("ld.global.cg.u32 %0, [%1];" : "=r"(cur) : "l"(&g_gb_phase));
            } while ((int)(cur - base) < ord);
        }
    }
    __syncthreads();
    __threadfence();
}

// ---------------------------------------------------------------------------
// GEMM A: xp[t][b][j] = sum_i input[b][t][i] * W_ih[j][i] + bias[j]
// M = B*T, N = HID, K = IN; 64x64 tile, 4x4 thread tile, f32x2 inner loop
// ---------------------------------------------------------------------------
__global__ void gemm_in_kernel(const float* __restrict__ in,
                               const float* __restrict__ W,
                               const float* __restrict__ bias) {
    __shared__ float sA[16][68];
    __shared__ float sB[16][68];
    const int m0 = blockIdx.y * 64;
    const int n0 = blockIdx.x * 64;
    const int tid = threadIdx.x;
    const int tx = tid & 15;
    const int ty = tid >> 4;
    const int r  = tid >> 2;
    const int kq = tid & 3;

    ull acc[4][2] = {};   // [m-row][j-pair]

    for (int k0 = 0; k0 < IN_; k0 += 16) {
        float4 va = *reinterpret_cast<const float4*>(&in[(size_t)(m0 + r) * IN_ + k0 + kq * 4]);
        float4 vb = *reinterpret_cast<const float4*>(&W [(size_t)(n0 + r) * IN_ + k0 + kq * 4]);
        sA[kq * 4 + 0][r] = va.x; sA[kq * 4 + 1][r] = va.y;
        sA[kq * 4 + 2][r] = va.z; sA[kq * 4 + 3][r] = va.w;
        sB[kq * 4 + 0][r] = vb.x; sB[kq * 4 + 1][r] = vb.y;
        sB[kq * 4 + 2][r] = vb.z; sB[kq * 4 + 3][r] = vb.w;
        __syncthreads();
        #pragma unroll
        for (int kk = 0; kk < 16; kk++) {
            float4 a = *reinterpret_cast<const float4*>(&sA[kk][ty * 4]);
            ulonglong2 b2 = *reinterpret_cast<const ulonglong2*>(&sB[kk][tx * 4]);
            ull a0, a1, a2, a3;
            DUP2(a0, a.x); DUP2(a1, a.y); DUP2(a2, a.z); DUP2(a3, a.w);
            FMA2(acc[0][0], a0, b2.x); FMA2(acc[0][1], a0, b2.y);
            FMA2(acc[1][0], a1, b2.x); FMA2(acc[1][1], a1, b2.y);
            FMA2(acc[2][0], a2, b2.x); FMA2(acc[2][1], a2, b2.y);
            FMA2(acc[3][0], a3, b2.x); FMA2(acc[3][1], a3, b2.y);
        }
        __syncthreads();
    }

    float4 bv = *reinterpret_cast<const float4*>(&bias[n0 + tx * 4]);
    #pragma unroll
    for (int i = 0; i < 4; i++) {
        const int m = m0 + ty * 4 + i;
        const int bb = m >> 9;        // m / T_
        const int tt = m & (T_ - 1);  // m % T_
        float4 v;
        UNPK2(v.x, v.y, acc[i][0]);
        UNPK2(v.z, v.w, acc[i][1]);
        v.x += bv.x; v.y += bv.y; v.z += bv.z; v.w += bv.w;
        *reinterpret_cast<float4*>(&g_xp[((size_t)tt * B_ + bb) * HID_ + n0 + tx * 4]) = v;
    }
}

// ---------------------------------------------------------------------------
// Persistent recurrence kernel: ONE launch for all 512 steps.
// grid = 128 blocks (jx=8 j-tiles of 128, ks=16 k-slices of 64), 512 threads.
// W_hh tile stays resident in SMEM for the whole sequence.
// Per step: split-K partials -> grid barrier -> reduce+tanh -> grid barrier.
// ---------------------------------------------------------------------------
__global__ __launch_bounds__(512, 1) void rnn_persistent(const float* __restrict__ Whh) {
    __shared__ float sW[KSL_][132];     // [k][j] resident W tile (64k x 128j)
    __shared__ float sh[2][16][68];     // staged h chunk [k][b]
    __shared__ float sred[64][9];       // reduce-phase transpose buffer

    const int tid = threadIdx.x;
    const int bid = blockIdx.x;
    const int jx  = bid & (JT_ - 1);    // 0..7
    const int ksi = bid >> 3;           // 0..15
    const int j0  = jx * 128;
    const int k0  = ksi * KSL_;
    const int tx  = tid & 31;           // j quad (0..31 -> 128 j)
    const int ty  = tid >> 5;           // b quad (0..15 -> 64 b)
    // reduce-phase mapping: block covers 64 j x 8 b
    const int jr0 = (bid & 15) * 64;
    const int br0 = (bid >> 4) * 8;
    const int rjj = tid & 63;
    const int rbb = tid >> 6;
    const int wrow = tid >> 3;          // 0..63 for hT writeback
    const int wcol = tid & 7;

    const unsigned base = *((volatile unsigned*)&g_gb_phase);
    int bar = 0;

    // ---- load resident W tile: sW[k][j] <- Whh[j0+jj][k0+k] ----
    #pragma unroll
    for (int q = 0; q < 4; q++) {
        const int idx = q * 512 + tid;      // 0..2047
        const int jj = idx >> 4;            // 0..127
        const int k4 = idx & 15;            // 0..15
        float4 w = *reinterpret_cast<const float4*>(&Whh[(size_t)(j0 + jj) * HID_ + k0 + k4 * 4]);
        sW[k4 * 4 + 0][jj] = w.x; sW[k4 * 4 + 1][jj] = w.y;
        sW[k4 * 4 + 2][jj] = w.z; sW[k4 * 4 + 3][jj] = w.w;
    }

    // ---- step 0: h0 = tanh(xp[0]) ----
    {
        const size_t off = (size_t)(br0 + rbb) * HID_ + jr0 + rjj;
        const float r = tanhf(g_xp[off]);
        g_hseq[off] = r;
        sred[rjj][rbb] = r;
        __syncthreads();
        g_hT[0][(jr0 + wrow) * B_ + br0 + wcol] = sred[wrow][wcol];
        grid_sync(base, ++bar);
    }

    for (int t = 1; t < T_; t++) {
        const float* __restrict__ hTp = g_hT[(t - 1) & 1];

        // stage chunk 0
        if (tid < 256) {
            const int rr = tid >> 4, c4 = tid & 15;
            *reinterpret_cast<float4*>(&sh[0][rr][c4 * 4]) =
                ldcg_f4(&hTp[(k0 + rr) * B_ + c4 * 4]);
        }

        ull acc[2][4] = {};   // [b-pair][j]  pair0=(b0,b1) pair1=(b2,b3)

        #pragma unroll
        for (int c = 0; c < KSL_ / 16; c++) {
            __syncthreads();
            if (c + 1 < KSL_ / 16 && tid < 256) {
                const int rr = tid >> 4, c4 = tid & 15;
                *reinterpret_cast<float4*>(&sh[(c + 1) & 1][rr][c4 * 4]) =
                    ldcg_f4(&hTp[(k0 + (c + 1) * 16 + rr) * B_ + c4 * 4]);
            }
            const int cb = c & 1;
            #pragma unroll
            for (int kk = 0; kk < 16; kk++) {
                ulonglong2 h2 = *reinterpret_cast<const ulonglong2*>(&sh[cb][kk][ty * 4]);
                float4 wv = *reinterpret_cast<const float4*>(&sW[c * 16 + kk][tx * 4]);
                ull w0, w1, w2, w3;
                DUP2(w0, wv.x); DUP2(w1, wv.y); DUP2(w2, wv.z); DUP2(w3, wv.w);
                FMA2(acc[0][0], h2.x, w0); FMA2(acc[0][1], h2.x, w1);
                FMA2(acc[0][2], h2.x, w2); FMA2(acc[0][3], h2.x, w3);
                FMA2(acc[1][0], h2.y, w0); FMA2(acc[1][1], h2.y, w1);
                FMA2(acc[1][2], h2.y, w2); FMA2(acc[1][3], h2.y, w3);
            }
        }

        // write split-K partials (L2): rows b = ty*4..ty*4+3, cols j0+tx*4..
        {
            float* __restrict__ pdst = g_part[ksi];
            float4 r0, r1, r2, r3;
            UNPK2(r0.x, r1.x, acc[0][0]); UNPK2(r0.y, r1.y, acc[0][1]);
            UNPK2(r0.z, r1.z, acc[0][2]); UNPK2(r0.w, r1.w, acc[0][3]);
            UNPK2(r2.x, r3.x, acc[1][0]); UNPK2(r2.y, r3.y, acc[1][1]);
            UNPK2(r2.z, r3.z, acc[1][2]); UNPK2(r2.w, r3.w, acc[1][3]);
            const size_t o = (size_t)(ty * 4) * HID_ + j0 + tx * 4;
            stcg_f4(&pdst[o],             r0);
            stcg_f4(&pdst[o + HID_],      r1);
            stcg_f4(&pdst[o + 2 * HID_],  r2);
            stcg_f4(&pdst[o + 3 * HID_],  r3);
        }

        grid_sync(base, ++bar);   // partials published

        // ---- reduce 16 partials + xp, tanh, write hseq[t] and hT[t] ----
        {
            const size_t off = (size_t)(br0 + rbb) * HID_ + jr0 + rjj;
            float s = g_xp[(size_t)t * B_ * HID_ + off];
            #pragma unroll
            for (int ks = 0; ks < KS_; ks++)
                s += ldcg_f(&g_part[ks][off]);
            const float r = tanhf(s);
            g_hseq[(size_t)t * B_ * HID_ + off] = r;
            sred[rjj][rbb] = r;
            __syncthreads();
            g_hT[t & 1][(jr0 + wrow) * B_ + br0 + wcol] = sred[wrow][wcol];
        }

        grid_sync(base, ++bar);   // hT[t] published
    }
}

// ---------------------------------------------------------------------------
// GEMM C: out[b][t][o] = sum_j hseq[t][b][j] * W_out[o][j] + b_out[o]
// ---------------------------------------------------------------------------
__global__ void gemm_out_kernel(const float* __restrict__ Wout,
                                const float* __restrict__ bout,
                                float* __restrict__ out) {
    __shared__ float sA[16][68];
    __shared__ float sB[16][68];
    const int m0 = blockIdx.y * 64;
    const int n0 = blockIdx.x * 64;
    const int tid = threadIdx.x;
    const int tx = tid & 15;
    const int ty = tid >> 4;
    const int r  = tid >> 2;
    const int kq = tid & 3;

    ull acc[4][2] = {};

    for (int k0 = 0; k0 < HID_; k0 += 16) {
        float4 va = *reinterpret_cast<const float4*>(&g_hseq[(size_t)(m0 + r) * HID_ + k0 + kq * 4]);
        float4 vb = *reinterpret_cast<const float4*>(&Wout  [(size_t)(n0 + r) * HID_ + k0 + kq * 4]);
        sA[kq * 4 + 0][r] = va.x; sA[kq * 4 + 1][r] = va.y;
        sA[kq * 4 + 2][r] = va.z; sA[kq * 4 + 3][r] = va.w;
        sB[kq * 4 + 0][r] = vb.x; sB[kq * 4 + 1][r] = vb.y;
        sB[kq * 4 + 2][r] = vb.z; sB[kq * 4 + 3][r] = vb.w;
        __syncthreads();
        #pragma unroll
        for (int kk = 0; kk < 16; kk++) {
            float4 a = *reinterpret_cast<const float4*>(&sA[kk][ty * 4]);
            ulonglong2 b2 = *reinterpret_cast<const ulonglong2*>(&sB[kk][tx * 4]);
            ull a0, a1, a2, a3;
            DUP2(a0, a.x); DUP2(a1, a.y); DUP2(a2, a.z); DUP2(a3, a.w);
            FMA2(acc[0][0], a0, b2.x); FMA2(acc[0][1], a0, b2.y);
            FMA2(acc[1][0], a1, b2.x); FMA2(acc[1][1], a1, b2.y);
            FMA2(acc[2][0], a2, b2.x); FMA2(acc[2][1], a2, b2.y);
            FMA2(acc[3][0], a3, b2.x); FMA2(acc[3][1], a3, b2.y);
        }
        __syncthreads();
    }

    float4 bv = *reinterpret_cast<const float4*>(&bout[n0 + tx * 4]);
    #pragma unroll
    for (int i = 0; i < 4; i++) {
        const int m = m0 + ty * 4 + i;
        const int tt = m >> 6;        // m / B_
        const int bb = m & (B_ - 1);  // m % B_
        float4 v;
        UNPK2(v.x, v.y, acc[i][0]);
        UNPK2(v.z, v.w, acc[i][1]);
        v.x += bv.x; v.y += bv.y; v.z += bv.z; v.w += bv.w;
        *reinterpret_cast<float4*>(&out[((size_t)bb * T_ + tt) * OUT_ + n0 + tx * 4]) = v;
    }
}

// ---------------------------------------------------------------------------
extern "C" void kernel_launch(void* const* d_in, const int* in_sizes, int n_in,
                              void* d_out, int out_size) {
    const float* input = (const float*)d_in[0];
    const float* W_ih  = (const float*)d_in[1];
    const float* W_hh  = (const float*)d_in[2];
    const float* bias  = (const float*)d_in[3];
    const float* W_out = (const float*)d_in[4];
    const float* b_out = (const float*)d_in[5];
    float* out = (float*)d_out;

    // 1) input projection for all timesteps
    gemm_in_kernel<<<dim3(HID_ / 64, (B_ * T_) / 64), 256>>>(input, W_ih, bias);

    // 2) persistent recurrence: one kernel for all 512 steps (3 graph nodes total)
    rnn_persistent<<<NBLK, 512>>>(W_hh);

    // 3) output projection for all timesteps
    gemm_out_kernel<<<dim3(OUT_ / 64, (B_ * T_) / 64), 256>>>(W_out, b_out, out);
}

// round 5
// speedup vs baseline: 2.2442x; 1.0003x over previous
#include <cuda_runtime.h>
#include <math.h>

// Problem dims (fixed for this dataset)
#define B_   64
#define T_   512
#define IN_  512
#define HID_ 1024
#define OUT_ 512
#define NBLK 128        // persistent blocks (<= 148 SMs -> all co-resident)
#define KS_  16         // split-K slices (64 k each)
#define KSL_ 64
#define JT_  8          // j-tiles of 128

typedef unsigned long long ull;

// packed fp32x2 FMA helpers (bit-identical to scalar FFMA)
#define FMA2(d, a, b) asm("fma.rn.f32x2 %0, %1, %2, %0;" : "+l"(d) : "l"(a), "l"(b))
#define DUP2(d, s)    asm("mov.b64 %0, {%1, %1};" : "=l"(d) : "r"(__float_as_uint(s)))
#define UNPK2(lo, hi, s) asm("mov.b64 {%0, %1}, %2;" : "=f"(lo), "=f"(hi) : "l"(s))

// Scratch (allocation-free contract: __device__ globals; BSS zero-init)
__device__ float g_xp[(size_t)T_ * B_ * HID_];    // [t][b][j]
__device__ float g_hseq[(size_t)T_ * B_ * HID_];  // [t][b][j]
__device__ float g_hT[2][HID_ * B_];              // ping-pong transposed hidden [j][b]
__device__ float g_part[KS_][B_ * HID_];          // split-K partials
__device__ unsigned g_gb_cnt;                     // barrier arrivals (returns to 0)
__device__ unsigned g_gb_phase;                   // barrier phase (monotonic across replays)

__device__ __forceinline__ float ldcg_f(const float* p) {
    float v; asm volatile("ld.global.cg.f32 %0, [%1];" : "=f"(v) : "l"(p)); return v;
}
__device__ __forceinline__ float4 ldcg_f4(const float* p) {
    float4 v;
    asm volatile("ld.global.cg.v4.f32 {%0,%1,%2,%3}, [%4];"
                 : "=f"(v.x), "=f"(v.y), "=f"(v.z), "=f"(v.w) : "l"(p));
    return v;
}
__device__ __forceinline__ void stcg_f4(float* p, float4 v) {
    asm volatile("st.global.cg.v4.f32 [%0], {%1,%2,%3,%4};"
                 :: "l"(p), "f"(v.x), "f"(v.y), "f"(v.z), "f"(v.w));
}

// all-resident grid barrier; base = phase snapshot at kernel entry, ord = 1,2,3...
__device__ __forceinline__ void grid_sync(unsigned base, int ord) {
    __threadfence();           // publish this thread's prior writes
    __syncthreads();
    if (threadIdx.x == 0) {
        unsigned old = atomicAdd(&g_gb_cnt, 1);
        if (old == NBLK - 1) {
            atomicExch(&g_gb_cnt, 0);   // reset BEFORE release -> replay-safe
            __threadfence();
            atomicAdd(&g_gb_phase, 1);
        } else {
            unsigned cur;
            do {
                __nanosleep(64);
                asm volatile("ld.global.cg.u32 %0, [%1];" : "=r"(cur) : "l"(&g_gb_phase));
            } while ((int)(cur - base) < ord);
        }
    }
    __syncthreads();
    __threadfence();
}

// ---------------------------------------------------------------------------
// GEMM A: xp[t][b][j] = sum_i input[b][t][i] * W_ih[j][i] + bias[j]
// M = B*T, N = HID, K = IN; 64x64 tile, 4x4 thread tile, f32x2 inner loop
// ---------------------------------------------------------------------------
__global__ void gemm_in_kernel(const float* __restrict__ in,
                               const float* __restrict__ W,
                               const float* __restrict__ bias) {
    __shared__ float sA[16][68];
    __shared__ float sB[16][68];
    const int m0 = blockIdx.y * 64;
    const int n0 = blockIdx.x * 64;
    const int tid = threadIdx.x;
    const int tx = tid & 15;
    const int ty = tid >> 4;
    const int r  = tid >> 2;
    const int kq = tid & 3;

    ull acc[4][2] = {};   // [m-row][j-pair]

    for (int k0 = 0; k0 < IN_; k0 += 16) {
        float4 va = *reinterpret_cast<const float4*>(&in[(size_t)(m0 + r) * IN_ + k0 + kq * 4]);
        float4 vb = *reinterpret_cast<const float4*>(&W [(size_t)(n0 + r) * IN_ + k0 + kq * 4]);
        sA[kq * 4 + 0][r] = va.x; sA[kq * 4 + 1][r] = va.y;
        sA[kq * 4 + 2][r] = va.z; sA[kq * 4 + 3][r] = va.w;
        sB[kq * 4 + 0][r] = vb.x; sB[kq * 4 + 1][r] = vb.y;
        sB[kq * 4 + 2][r] = vb.z; sB[kq * 4 + 3][r] = vb.w;
        __syncthreads();
        #pragma unroll
        for (int kk = 0; kk < 16; kk++) {
            float4 a = *reinterpret_cast<const float4*>(&sA[kk][ty * 4]);
            ulonglong2 b2 = *reinterpret_cast<const ulonglong2*>(&sB[kk][tx * 4]);
            ull a0, a1, a2, a3;
            DUP2(a0, a.x); DUP2(a1, a.y); DUP2(a2, a.z); DUP2(a3, a.w);
            FMA2(acc[0][0], a0, b2.x); FMA2(acc[0][1], a0, b2.y);
            FMA2(acc[1][0], a1, b2.x); FMA2(acc[1][1], a1, b2.y);
            FMA2(acc[2][0], a2, b2.x); FMA2(acc[2][1], a2, b2.y);
            FMA2(acc[3][0], a3, b2.x); FMA2(acc[3][1], a3, b2.y);
        }
        __syncthreads();
    }

    float4 bv = *reinterpret_cast<const float4*>(&bias[n0 + tx * 4]);
    #pragma unroll
    for (int i = 0; i < 4; i++) {
        const int m = m0 + ty * 4 + i;
        const int bb = m >> 9;        // m / T_
        const int tt = m & (T_ - 1);  // m % T_
        float4 v;
        UNPK2(v.x, v.y, acc[i][0]);
        UNPK2(v.z, v.w, acc[i][1]);
        v.x += bv.x; v.y += bv.y; v.z += bv.z; v.w += bv.w;
        *reinterpret_cast<float4*>(&g_xp[((size_t)tt * B_ + bb) * HID_ + n0 + tx * 4]) = v;
    }
}

// ---------------------------------------------------------------------------
// Persistent recurrence kernel: ONE launch for all 512 steps.
// grid = 128 blocks (jx=8 j-tiles of 128, ks=16 k-slices of 64), 512 threads.
// W_hh tile stays resident in SMEM for the whole sequence.
// Per step: split-K partials -> grid barrier -> reduce+tanh -> grid barrier.
// ---------------------------------------------------------------------------
__global__ __launch_bounds__(512, 1) void rnn_persistent(const float* __restrict__ Whh) {
    __shared__ float sW[KSL_][132];     // [k][j] resident W tile (64k x 128j)
    __shared__ float sh[2][16][68];     // staged h chunk [k][b]
    __shared__ float sred[64][9];       // reduce-phase transpose buffer

    const int tid = threadIdx.x;
    const int bid = blockIdx.x;
    const int jx  = bid & (JT_ - 1);    // 0..7
    const int ksi = bid >> 3;           // 0..15
    const int j0  = jx * 128;
    const int k0  = ksi * KSL_;
    const int tx  = tid & 31;           // j quad (0..31 -> 128 j)
    const int ty  = tid >> 5;           // b quad (0..15 -> 64 b)
    // reduce-phase mapping: block covers 64 j x 8 b
    const int jr0 = (bid & 15) * 64;
    const int br0 = (bid >> 4) * 8;
    const int rjj = tid & 63;
    const int rbb = tid >> 6;
    const int wrow = tid >> 3;          // 0..63 for hT writeback
    const int wcol = tid & 7;

    const unsigned base = *((volatile unsigned*)&g_gb_phase);
    int bar = 0;

    // ---- load resident W tile: sW[k][j] <- Whh[j0+jj][k0+k] ----
    #pragma unroll
    for (int q = 0; q < 4; q++) {
        const int idx = q * 512 + tid;      // 0..2047
        const int jj = idx >> 4;            // 0..127
        const int k4 = idx & 15;            // 0..15
        float4 w = *reinterpret_cast<const float4*>(&Whh[(size_t)(j0 + jj) * HID_ + k0 + k4 * 4]);
        sW[k4 * 4 + 0][jj] = w.x; sW[k4 * 4 + 1][jj] = w.y;
        sW[k4 * 4 + 2][jj] = w.z; sW[k4 * 4 + 3][jj] = w.w;
    }

    // ---- step 0: h0 = tanh(xp[0]) ----
    {
        const size_t off = (size_t)(br0 + rbb) * HID_ + jr0 + rjj;
        const float r = tanhf(g_xp[off]);
        g_hseq[off] = r;
        sred[rjj][rbb] = r;
        __syncthreads();
        g_hT[0][(jr0 + wrow) * B_ + br0 + wcol] = sred[wrow][wcol];
        grid_sync(base, ++bar);
    }

    for (int t = 1; t < T_; t++) {
        const float* __restrict__ hTp = g_hT[(t - 1) & 1];

        // stage chunk 0
        if (tid < 256) {
            const int rr = tid >> 4, c4 = tid & 15;
            *reinterpret_cast<float4*>(&sh[0][rr][c4 * 4]) =
                ldcg_f4(&hTp[(k0 + rr) * B_ + c4 * 4]);
        }

        ull acc[2][4] = {};   // [b-pair][j]  pair0=(b0,b1) pair1=(b2,b3)

        #pragma unroll
        for (int c = 0; c < KSL_ / 16; c++) {
            __syncthreads();
            if (c + 1 < KSL_ / 16 && tid < 256) {
                const int rr = tid >> 4, c4 = tid & 15;
                *reinterpret_cast<float4*>(&sh[(c + 1) & 1][rr][c4 * 4]) =
                    ldcg_f4(&hTp[(k0 + (c + 1) * 16 + rr) * B_ + c4 * 4]);
            }
            const int cb = c & 1;
            #pragma unroll
            for (int kk = 0; kk < 16; kk++) {
                ulonglong2 h2 = *reinterpret_cast<const ulonglong2*>(&sh[cb][kk][ty * 4]);
                float4 wv = *reinterpret_cast<const float4*>(&sW[c * 16 + kk][tx * 4]);
                ull w0, w1, w2, w3;
                DUP2(w0, wv.x); DUP2(w1, wv.y); DUP2(w2, wv.z); DUP2(w3, wv.w);
                FMA2(acc[0][0], h2.x, w0); FMA2(acc[0][1], h2.x, w1);
                FMA2(acc[0][2], h2.x, w2); FMA2(acc[0][3], h2.x, w3);
                FMA2(acc[1][0], h2.y, w0); FMA2(acc[1][1], h2.y, w1);
                FMA2(acc[1][2], h2.y, w2); FMA2(acc[1][3], h2.y, w3);
            }
        }

        // write split-K partials (L2): rows b = ty*4..ty*4+3, cols j0+tx*4..
        {
            float* __restrict__ pdst = g_part[ksi];
            float4 r0, r1, r2, r3;
            UNPK2(r0.x, r1.x, acc[0][0]); UNPK2(r0.y, r1.y, acc[0][1]);
            UNPK2(r0.z, r1.z, acc[0][2]); UNPK2(r0.w, r1.w, acc[0][3]);
            UNPK2(r2.x, r3.x, acc[1][0]); UNPK2(r2.y, r3.y, acc[1][1]);
            UNPK2(r2.z, r3.z, acc[1][2]); UNPK2(r2.w, r3.w, acc[1][3]);
            const size_t o = (size_t)(ty * 4) * HID_ + j0 + tx * 4;
            stcg_f4(&pdst[o],             r0);
            stcg_f4(&pdst[o + HID_],      r1);
            stcg_f4(&pdst[o + 2 * HID_],  r2);
            stcg_f4(&pdst[o + 3 * HID_],  r3);
        }

        grid_sync(base, ++bar);   // partials published

        // ---- reduce 16 partials + xp, tanh, write hseq[t] and hT[t] ----
        {
            const size_t off = (size_t)(br0 + rbb) * HID_ + jr0 + rjj;
            float s = g_xp[(size_t)t * B_ * HID_ + off];
            #pragma unroll
            for (int ks = 0; ks < KS_; ks++)
                s += ldcg_f(&g_part[ks][off]);
            const float r = tanhf(s);
            g_hseq[(size_t)t * B_ * HID_ + off] = r;
            sred[rjj][rbb] = r;
            __syncthreads();
            g_hT[t & 1][(jr0 + wrow) * B_ + br0 + wcol] = sred[wrow][wcol];
        }

        grid_sync(base, ++bar);   // hT[t] published
    }
}

// ---------------------------------------------------------------------------
// GEMM C: out[b][t][o] = sum_j hseq[t][b][j] * W_out[o][j] + b_out[o]
// ---------------------------------------------------------------------------
__global__ void gemm_out_kernel(const float* __restrict__ Wout,
                                const float* __restrict__ bout,
                                float* __restrict__ out) {
    __shared__ float sA[16][68];
    __shared__ float sB[16][68];
    const int m0 = blockIdx.y * 64;
    const int n0 = blockIdx.x * 64;
    const int tid = threadIdx.x;
    const int tx = tid & 15;
    const int ty = tid >> 4;
    const int r  = tid >> 2;
    const int kq = tid & 3;

    ull acc[4][2] = {};

    for (int k0 = 0; k0 < HID_; k0 += 16) {
        float4 va = *reinterpret_cast<const float4*>(&g_hseq[(size_t)(m0 + r) * HID_ + k0 + kq * 4]);
        float4 vb = *reinterpret_cast<const float4*>(&Wout  [(size_t)(n0 + r) * HID_ + k0 + kq * 4]);
        sA[kq * 4 + 0][r] = va.x; sA[kq * 4 + 1][r] = va.y;
        sA[kq * 4 + 2][r] = va.z; sA[kq * 4 + 3][r] = va.w;
        sB[kq * 4 + 0][r] = vb.x; sB[kq * 4 + 1][r] = vb.y;
        sB[kq * 4 + 2][r] = vb.z; sB[kq * 4 + 3][r] = vb.w;
        __syncthreads();
        #pragma unroll
        for (int kk = 0; kk < 16; kk++) {
            float4 a = *reinterpret_cast<const float4*>(&sA[kk][ty * 4]);
            ulonglong2 b2 = *reinterpret_cast<const ulonglong2*>(&sB[kk][tx * 4]);
            ull a0, a1, a2, a3;
            DUP2(a0, a.x); DUP2(a1, a.y); DUP2(a2, a.z); DUP2(a3, a.w);
            FMA2(acc[0][0], a0, b2.x); FMA2(acc[0][1], a0, b2.y);
            FMA2(acc[1][0], a1, b2.x); FMA2(acc[1][1], a1, b2.y);
            FMA2(acc[2][0], a2, b2.x); FMA2(acc[2][1], a2, b2.y);
            FMA2(acc[3][0], a3, b2.x); FMA2(acc[3][1], a3, b2.y);
        }
        __syncthreads();
    }

    float4 bv = *reinterpret_cast<const float4*>(&bout[n0 + tx * 4]);
    #pragma unroll
    for (int i = 0; i < 4; i++) {
        const int m = m0 + ty * 4 + i;
        const int tt = m >> 6;        // m / B_
        const int bb = m & (B_ - 1);  // m % B_
        float4 v;
        UNPK2(v.x, v.y, acc[i][0]);
        UNPK2(v.z, v.w, acc[i][1]);
        v.x += bv.x; v.y += bv.y; v.z += bv.z; v.w += bv.w;
        *reinterpret_cast<float4*>(&out[((size_t)bb * T_ + tt) * OUT_ + n0 + tx * 4]) = v;
    }
}

// ---------------------------------------------------------------------------
extern "C" void kernel_launch(void* const* d_in, const int* in_sizes, int n_in,
                              void* d_out, int out_size) {
    const float* input = (const float*)d_in[0];
    const float* W_ih  = (const float*)d_in[1];
    const float* W_hh  = (const float*)d_in[2];
    const float* bias  = (const float*)d_in[3];
    const float* W_out = (const float*)d_in[4];
    const float* b_out = (const float*)d_in[5];
    float* out = (float*)d_out;

    // 1) input projection for all timesteps
    gemm_in_kernel<<<dim3(HID_ / 64, (B_ * T_) / 64), 256>>>(input, W_ih, bias);

    // 2) persistent recurrence: one kernel for all 512 steps (3 graph nodes total)
    rnn_persistent<<<NBLK, 512>>>(W_hh);

    // 3) output projection for all timesteps
    gemm_out_kernel<<<dim3(OUT_ / 64, (B_ * T_) / 64), 256>>>(W_out, b_out, out);
}

// round 10
// speedup vs baseline: 2.3214x; 1.0344x over previous
#include <cuda_runtime.h>
#include <math.h>

// Problem dims (fixed for this dataset)
#define B_   64
#define T_   512
#define IN_  512
#define HID_ 1024
#define OUT_ 512
#define NBLK 128        // persistent blocks (<=148 SMs -> all co-resident)
#define KS_  16         // split-K slices (64 k each)
#define JT_  8          // j-tiles of 128

typedef unsigned long long ull;

// packed fp32x2 FMA helpers (bit-identical to scalar FFMA)
#define FMA2(d, a, b) asm("fma.rn.f32x2 %0, %1, %2, %0;" : "+l"(d) : "l"(a), "l"(b))
#define DUP2(d, s)    asm("mov.b64 %0, {%1, %1};" : "=l"(d) : "r"(__float_as_uint(s)))
#define UNPK2(lo, hi, s) asm("mov.b64 {%0, %1}, %2;" : "=f"(lo), "=f"(hi) : "l"(s))

// Scratch (allocation-free contract: __device__ globals; BSS zero-init)
__device__ float g_xp[(size_t)T_ * B_ * HID_];     // [t][b][j]
__device__ float g_hseq[(size_t)T_ * B_ * HID_];   // [t][b][j]
__device__ float g_hT[2][HID_ * B_];               // ping-pong transposed hidden [j][b]
__device__ float g_part[2][KS_][B_ * HID_];        // double-buffered split-K partials
__device__ unsigned g_flags[NBLK];                 // per-block arrival flags (monotonic)
__device__ unsigned g_phase;                       // release word (monotonic)

__device__ __forceinline__ float ldcg_f(const float* p) {
    float v; asm volatile("ld.global.cg.f32 %0, [%1];" : "=f"(v) : "l"(p)); return v;
}
__device__ __forceinline__ float4 ldcg_f4(const float* p) {
    float4 v;
    asm volatile("ld.global.cg.v4.f32 {%0,%1,%2,%3}, [%4];"
                 : "=f"(v.x), "=f"(v.y), "=f"(v.z), "=f"(v.w) : "l"(p));
    return v;
}
__device__ __forceinline__ void stcg_f4(float* p, float4 v) {
    asm volatile("st.global.cg.v4.f32 [%0], {%1,%2,%3,%4};"
                 :: "l"(p), "f"(v.x), "f"(v.y), "f"(v.z), "f"(v.w));
}
__device__ __forceinline__ unsigned ld_acq(const unsigned* p) {
    unsigned v; asm volatile("ld.acquire.gpu.u32 %0, [%1];" : "=r"(v) : "l"(p)); return v;
}
__device__ __forceinline__ void st_rel(unsigned* p, unsigned v) {
    asm volatile("st.release.gpu.u32 [%0], %1;" :: "l"(p), "r"(v));
}

// Flag-array grid barrier: no contended atomics. Block 0 collects all flags,
// bumps the phase word. Values are monotonic (base + ord) -> graph-replay-safe,
// nothing to reset. Acquire/release on the signal words.
__device__ __forceinline__ void grid_barrier(unsigned base, unsigned ord) {
    const unsigned tgt = base + ord;
    const int tid = threadIdx.x;
    __threadfence();       // publish this block's data writes
    __syncthreads();
    if (blockIdx.x == 0) {
        if (tid >= 1 && tid < NBLK) {
            while ((int)(ld_acq(&g_flags[tid]) - tgt) < 0) __nanosleep(32);
        }
        __syncthreads();
        if (tid == 0) st_rel(&g_phase, tgt);
    } else {
        if (tid == 0) {
            st_rel(&g_flags[blockIdx.x], tgt);
            while ((int)(ld_acq(&g_phase) - tgt) < 0) __nanosleep(32);
        }
        __syncthreads();
    }
    __threadfence();
}

// ---------------------------------------------------------------------------
// Big GEMM (both projections): C[m,n] = sum_k A[m,k]*Bm[n,k] + bias[n]
// 128x128 block tile, 512 threads, 8m x 4n per thread, f32x2, double-buffered.
// MODE 0: A = param (input), write g_xp with m=(b*T+t) -> [t][b][n]
// MODE 1: A = g_hseq (device symbol, resolved IN DEVICE CODE), write C with
//         m=(t*B+b) -> [b][t][n].
// ---------------------------------------------------------------------------
template<int KDIM, int MODE>
__global__ __launch_bounds__(512) void big_gemm(const float* __restrict__ A_param,
                                                const float* __restrict__ Bm,
                                                const float* __restrict__ bias,
                                                float* __restrict__ C) {
    // device-side resolution of the A operand (host code must NOT touch __device__ symbols)
    const float* __restrict__ A = (MODE == 1) ? g_hseq : A_param;

    __shared__ float sA[2][16][132];
    __shared__ float sB[2][16][132];
    const int m0 = blockIdx.y * 128;
    const int n0 = blockIdx.x * 128;
    const int tid = threadIdx.x;
    const int srow = tid >> 2;     // 0..127 staging row
    const int skq  = tid & 3;      // 0..3   staging k-quad
    const int tmr  = tid >> 5;     // 0..15  m-group (8 rows)
    const int tnr  = tid & 31;     // 0..31  n-group (4 cols)

    // prologue: load chunk 0 -> regs -> buf 0
    float4 ra = *reinterpret_cast<const float4*>(&A [(size_t)(m0 + srow) * KDIM + skq * 4]);
    float4 rb = *reinterpret_cast<const float4*>(&Bm[(size_t)(n0 + srow) * KDIM + skq * 4]);
    sA[0][skq * 4 + 0][srow] = ra.x; sA[0][skq * 4 + 1][srow] = ra.y;
    sA[0][skq * 4 + 2][srow] = ra.z; sA[0][skq * 4 + 3][srow] = ra.w;
    sB[0][skq * 4 + 0][srow] = rb.x; sB[0][skq * 4 + 1][srow] = rb.y;
    sB[0][skq * 4 + 2][srow] = rb.z; sB[0][skq * 4 + 3][srow] = rb.w;
    __syncthreads();

    ull acc[8][2] = {};
    const int NC = KDIM / 16;

    for (int c = 0; c < NC; c++) {
        if (c + 1 < NC) {
            ra = *reinterpret_cast<const float4*>(&A [(size_t)(m0 + srow) * KDIM + (c + 1) * 16 + skq * 4]);
            rb = *reinterpret_cast<const float4*>(&Bm[(size_t)(n0 + srow) * KDIM + (c + 1) * 16 + skq * 4]);
        }
        const int cb = c & 1;
        #pragma unroll
        for (int kk = 0; kk < 16; kk++) {
            float4 a0v = *reinterpret_cast<const float4*>(&sA[cb][kk][tmr * 8]);
            float4 a1v = *reinterpret_cast<const float4*>(&sA[cb][kk][tmr * 8 + 4]);
            ulonglong2 bv = *reinterpret_cast<const ulonglong2*>(&sB[cb][kk][tnr * 4]);
            ull a_[8];
            DUP2(a_[0], a0v.x); DUP2(a_[1], a0v.y); DUP2(a_[2], a0v.z); DUP2(a_[3], a0v.w);
            DUP2(a_[4], a1v.x); DUP2(a_[5], a1v.y); DUP2(a_[6], a1v.z); DUP2(a_[7], a1v.w);
            #pragma unroll
            for (int mi = 0; mi < 8; mi++) {
                FMA2(acc[mi][0], a_[mi], bv.x);
                FMA2(acc[mi][1], a_[mi], bv.y);
            }
        }
        if (c + 1 < NC) {
            const int nb = (c + 1) & 1;
            sA[nb][skq * 4 + 0][srow] = ra.x; sA[nb][skq * 4 + 1][srow] = ra.y;
            sA[nb][skq * 4 + 2][srow] = ra.z; sA[nb][skq * 4 + 3][srow] = ra.w;
            sB[nb][skq * 4 + 0][srow] = rb.x; sB[nb][skq * 4 + 1][srow] = rb.y;
            sB[nb][skq * 4 + 2][srow] = rb.z; sB[nb][skq * 4 + 3][srow] = rb.w;
        }
        __syncthreads();
    }

    const float4 bv4 = *reinterpret_cast<const float4*>(&bias[n0 + tnr * 4]);
    #pragma unroll
    for (int mi = 0; mi < 8; mi++) {
        const int m = m0 + tmr * 8 + mi;
        float4 v;
        UNPK2(v.x, v.y, acc[mi][0]);
        UNPK2(v.z, v.w, acc[mi][1]);
        v.x += bv4.x; v.y += bv4.y; v.z += bv4.z; v.w += bv4.w;
        if (MODE == 0) {
            const int bb = m >> 9;        // m / T_
            const int tt = m & (T_ - 1);
            *reinterpret_cast<float4*>(&g_xp[((size_t)tt * B_ + bb) * HID_ + n0 + tnr * 4]) = v;
        } else {
            const int tt = m >> 6;        // m / B_
            const int bb = m & (B_ - 1);
            *reinterpret_cast<float4*>(&C[((size_t)bb * T_ + tt) * OUT_ + n0 + tnr * 4]) = v;
        }
    }
}

// ---------------------------------------------------------------------------
// Persistent recurrence: ONE launch for all 512 steps.
// 128 blocks (jx 0..7: j-tile 128, ksi 0..15: k-slice 64), 512 threads.
// sW resident in SMEM (32KB) for the whole sequence. Per step:
//   stage shh slice (16KB, ldcg) -> sync-free GEMM -> partials (L2, ping-pong)
//   -> barrier -> disjoint reduce + tanh -> hT + hseq -> barrier.
// ---------------------------------------------------------------------------
__global__ __launch_bounds__(512, 1) void rnn_persistent(const float* __restrict__ Whh) {
    __shared__ float sW[64][128];   // [k][j] resident (32KB)
    __shared__ float sh[64][64];    // [k][b] per-step slice (16KB); sred overlays

    const int tid = threadIdx.x;
    const int bid = blockIdx.x;
    const int jx  = bid & (JT_ - 1);
    const int ksi = bid >> 3;
    const int j0  = jx * 128;
    const int k0  = ksi * 64;
    const int w    = tid >> 5;
    const int lane = tid & 31;
    // square warp footprint: 8 j-quads (128B) x 4 b-quads (64B) per warp
    const int tjq = (w & 3) * 8 + (lane & 7);    // 0..31 -> j = j0 + tjq*4
    const int tbq = (w >> 2) * 4 + (lane >> 3);  // 0..15 -> b = tbq*4
    // disjoint reduce region: 64 j x 8 b per block
    const int rj0 = (bid & 15) * 64;
    const int rb0 = (bid >> 4) * 8;
    const int rj = rj0 + (tid & 63);
    const int rb = rb0 + (tid >> 6);
    float* sred = &sh[0][0];        // overlay: 64 x 9 floats (sh dead during reduce)

    const unsigned base = ld_acq(&g_phase);
    unsigned ord = 0;

    // resident W tile: sW[k][j] <- Whh[j0+jj][k0+k]
    #pragma unroll
    for (int q = 0; q < 4; q++) {
        const int idx = q * 512 + tid;   // 2048 float4
        const int jj = idx >> 4;
        const int kq = idx & 15;
        float4 wv = *reinterpret_cast<const float4*>(&Whh[(size_t)(j0 + jj) * HID_ + k0 + kq * 4]);
        sW[kq * 4 + 0][jj] = wv.x; sW[kq * 4 + 1][jj] = wv.y;
        sW[kq * 4 + 2][jj] = wv.z; sW[kq * 4 + 3][jj] = wv.w;
    }

    // ---- step 0: h0 = tanh(xp[0]) over this block's disjoint region ----
    {
        const size_t off = (size_t)rb * HID_ + rj;
        const float v = tanhf(g_xp[off]);
        g_hseq[off] = v;
        sred[(tid & 63) * 9 + (tid >> 6)] = v;
        __syncthreads();
        const int jrow = tid >> 3, bcol = tid & 7;
        g_hT[0][(rj0 + jrow) * B_ + rb0 + bcol] = sred[jrow * 9 + bcol];
    }
    grid_barrier(base, ++ord);

    for (int t = 1; t < T_; t++) {
        const float* __restrict__ hTp = g_hT[(t - 1) & 1];

        // stage h slice: sh[k][b] <- hT[k0+k][b]
        #pragma unroll
        for (int q = 0; q < 2; q++) {
            const int idx = q * 512 + tid;   // 1024 float4
            const int k = idx >> 4;
            const int b4 = idx & 15;
            float4 hv = ldcg_f4(&hTp[(k0 + k) * B_ + b4 * 4]);
            *reinterpret_cast<float4*>(&sh[k][b4 * 4]) = hv;
        }
        __syncthreads();

        // sync-free GEMM over resident smem
        ull acc[2][4] = {};
        #pragma unroll 16
        for (int kk = 0; kk < 64; kk++) {
            ulonglong2 h2 = *reinterpret_cast<const ulonglong2*>(&sh[kk][tbq * 4]);
            float4 wv = *reinterpret_cast<const float4*>(&sW[kk][tjq * 4]);
            ull w0, w1, w2, w3;
            DUP2(w0, wv.x); DUP2(w1, wv.y); DUP2(w2, wv.z); DUP2(w3, wv.w);
            FMA2(acc[0][0], h2.x, w0); FMA2(acc[0][1], h2.x, w1);
            FMA2(acc[0][2], h2.x, w2); FMA2(acc[0][3], h2.x, w3);
            FMA2(acc[1][0], h2.y, w0); FMA2(acc[1][1], h2.y, w1);
            FMA2(acc[1][2], h2.y, w2); FMA2(acc[1][3], h2.y, w3);
        }

        // write partials (ping-pong buffer by t parity)
        {
            float* __restrict__ pdst = g_part[t & 1][ksi];
            float4 r0, r1, r2, r3;
            UNPK2(r0.x, r1.x, acc[0][0]); UNPK2(r0.y, r1.y, acc[0][1]);
            UNPK2(r0.z, r1.z, acc[0][2]); UNPK2(r0.w, r1.w, acc[0][3]);
            UNPK2(r2.x, r3.x, acc[1][0]); UNPK2(r2.y, r3.y, acc[1][1]);
            UNPK2(r2.z, r3.z, acc[1][2]); UNPK2(r2.w, r3.w, acc[1][3]);
            const size_t o = (size_t)(tbq * 4) * HID_ + j0 + tjq * 4;
            stcg_f4(&pdst[o],            r0);
            stcg_f4(&pdst[o + HID_],     r1);
            stcg_f4(&pdst[o + 2 * HID_], r2);
            stcg_f4(&pdst[o + 3 * HID_], r3);
        }

        grid_barrier(base, ++ord);   // all partials published

        // disjoint reduce + tanh; write hseq[t] and transposed hT[t&1]
        {
            const size_t off = (size_t)rb * HID_ + rj;
            float s = g_xp[(size_t)t * B_ * HID_ + off];
            #pragma unroll
            for (int ks = 0; ks < KS_; ks++)
                s += ldcg_f(&g_part[t & 1][ks][off]);
            const float v = tanhf(s);
            g_hseq[(size_t)t * B_ * HID_ + off] = v;
            sred[(tid & 63) * 9 + (tid >> 6)] = v;
            __syncthreads();
            const int jrow = tid >> 3, bcol = tid & 7;
            g_hT[t & 1][(rj0 + jrow) * B_ + rb0 + bcol] = sred[jrow * 9 + bcol];
        }

        grid_barrier(base, ++ord);   // hT[t] published
    }
}

// ---------------------------------------------------------------------------
extern "C" void kernel_launch(void* const* d_in, const int* in_sizes, int n_in,
                              void* d_out, int out_size) {
    const float* input = (const float*)d_in[0];
    const float* W_ih  = (const float*)d_in[1];
    const float* W_hh  = (const float*)d_in[2];
    const float* bias  = (const float*)d_in[3];
    const float* W_out = (const float*)d_in[4];
    const float* b_out = (const float*)d_in[5];
    float* out = (float*)d_out;

    // 1) input projection for all timesteps
    big_gemm<IN_, 0><<<dim3(HID_ / 128, (B_ * T_) / 128), 512>>>(input, W_ih, bias, nullptr);

    // 2) persistent recurrence: one kernel for all 512 steps
    rnn_persistent<<<NBLK, 512>>>(W_hh);

    // 3) output projection for all timesteps (A = g_hseq resolved in device code)
    big_gemm<HID_, 1><<<dim3(OUT_ / 128, (B_ * T_) / 128), 512>>>(nullptr, W_out, b_out, out);
}